// round 10
// baseline (speedup 1.0000x reference)
#include <cuda_runtime.h>
#include <cuda_fp16.h>
#include <cstdint>

// RNN: h_t = tanh([h_{t-1} | x_t] @ [W_hh | W_ih]^T + b), out = h_T @ W_out^T + b_out
// fp16-split 3-pass mma.m16n8k16; W = W_hi + W_lo/2048, state likewise.
// Round 10: k-split warp pairs. 8 warps/CTA: pair=wid>>1 (m-group, m=16), sub=wid&1
// (chunks sub*3..sub*3+2). 24 W regs/warp -> fits 64-reg cap at occ 4 => 8 warps/SMSP.
// Partials combined via smem scratch + named barrier per pair.

#define BATCH    4096
#define TSTEPS   512
#define IN_DIM   28
#define HID      64
#define OUT_DIM  10
#define KCOMB    96           // 64 h + 28 x + 4 pad
#define BTILE    8
#define NTHREADS 256          // 8 warps
#define S        68           // words per row; 68 % 32 == 4 -> conflict-free maps
#define PLANE    (BTILE * S)  // 544 words per plane
#define STATE_WORDS (4 * PLANE)         // 2176: [buf0_hi|buf0_lo|buf1_hi|buf1_lo]
#define SCRATCH  2176                   // partial-sum scratch: 4*4*32 = 512 words
#define WOUT_OFF 2688                   // W_out stage for epilogue
#define BIAS_OFF (HID * KCOMB)          // 6144 (stage area, overlaid by state later)
#define SMEM_WORDS (BIAS_OFF + HID)     // 6208
#define SMEM_BYTES (SMEM_WORDS * 4)     // 24832 B

#define INV2048  4.8828125e-4f

__device__ __forceinline__ float fast_tanh(float v) {
    float e = __expf(2.0f * v);
    return 1.0f - __fdividef(2.0f, e + 1.0f);
}

__device__ __forceinline__ uint32_t pack2(__half lo, __half hi) {
    __half2 h = __halves2half2(lo, hi);
    return *reinterpret_cast<uint32_t*>(&h);
}

__device__ __forceinline__ void mma16(float* d, const uint32_t* a, const uint32_t* b) {
    asm volatile(
        "mma.sync.aligned.m16n8k16.row.col.f32.f16.f16.f32 "
        "{%0,%1,%2,%3}, {%4,%5,%6,%7}, {%8,%9}, {%0,%1,%2,%3};"
        : "+f"(d[0]), "+f"(d[1]), "+f"(d[2]), "+f"(d[3])
        : "r"(a[0]), "r"(a[1]), "r"(a[2]), "r"(a[3]), "r"(b[0]), "r"(b[1]));
}

__global__ void __launch_bounds__(NTHREADS, 4)
rnn_ks_kernel(const float* __restrict__ x,
              const float* __restrict__ W_ih,
              const float* __restrict__ W_hh,
              const float* __restrict__ b_ih,
              const float* __restrict__ b_hh,
              const float* __restrict__ W_out,
              const float* __restrict__ b_out,
              float* __restrict__ out)
{
    extern __shared__ float sm[];
    uint32_t* usm = (uint32_t*)sm;

    const int tid  = threadIdx.x;
    const int b0   = blockIdx.x * BTILE;
    const int lane = tid & 31;
    const int wid  = tid >> 5;
    const int pair = wid >> 1;     // m-group: W rows [pair*16, pair*16+16)
    const int sub  = wid & 1;      // k-half: chunks [sub*3, sub*3+3)
    const int gid  = lane >> 2;
    const int tig  = lane & 3;
    const int m0   = pair * 16;
    const int c0   = sub * 3;

    // ---- Stage combined weight Wc[64][96] fp32 at sm[0..6144) + bias ----
    for (int idx = tid; idx < HID * KCOMB; idx += NTHREADS) {
        int j = idx / KCOMB, k = idx % KCOMB;
        float v = 0.0f;
        if (k < HID)               v = W_hh[j * HID + k];
        else if (k < HID + IN_DIM) v = W_ih[j * IN_DIM + (k - HID)];
        sm[idx] = v;
    }
    if (tid < HID) sm[BIAS_OFF + tid] = b_ih[tid] + b_hh[tid];
    __syncthreads();

    // ---- W fragments: 3 chunks per warp (m16k16 each), hi + scaled-lo fp16 ----
    uint32_t whi[3][4], wlo[3][4];
#pragma unroll
    for (int c = 0; c < 3; c++) {
        int cc = c0 + c;
#pragma unroll
        for (int r = 0; r < 4; r++) {
            int row = m0 + gid + (r & 1) * 8;
            int k0  = cc * 16 + 2 * tig + (r >> 1) * 8;
            float va = sm[row * KCOMB + k0];
            float vb = sm[row * KCOMB + k0 + 1];
            __half ha = __float2half_rn(va), hb = __float2half_rn(vb);
            whi[c][r] = pack2(ha, hb);
            wlo[c][r] = pack2(
                __float2half_rn((va - __half2float(ha)) * 2048.0f),
                __float2half_rn((vb - __half2float(hb)) * 2048.0f));
        }
    }
    // bias added once per pair: only in sub0's accA seed
    const float bias0 = sub ? 0.0f : sm[BIAS_OFF + m0 + gid];
    const float bias1 = sub ? 0.0f : sm[BIAS_OFF + m0 + gid + 8];
    __syncthreads();   // frag reads done; stage area reused as state

    // ---- Zero state double-buffers overlaid on stage area ----
    for (int idx = tid; idx < STATE_WORDS; idx += NTHREADS) sm[idx] = 0.0f;

    // ---- x loader: sub1 warps, lidx = pair*32+lane < 56; one float4 per step ----
    const int  lidx = pair * 32 + lane;
    const bool isld = (sub == 1) && (lidx < 56);
    const int  xn = isld ? lidx / 7 : 0;       // row 0..7
    const int  xq = isld ? lidx % 7 : 0;
    const float4* xp4 = (const float4*)(x + (size_t)(b0 + xn) * TSTEPS * IN_DIM) + xq;

    float4 xr = make_float4(0, 0, 0, 0);
    if (isld) xr = xp4[0];                    // t = 0
    __syncthreads();                          // zero-fill visible

    auto store_x = [&](int p) {
        int hb = (p * 2) * PLANE + xn * S + 32 + 2 * xq;
        __half h0 = __float2half_rn(xr.x), h1 = __float2half_rn(xr.y);
        __half h2 = __float2half_rn(xr.z), h3 = __float2half_rn(xr.w);
        usm[hb]     = pack2(h0, h1);
        usm[hb + 1] = pack2(h2, h3);
        usm[hb + PLANE]     = pack2(__float2half_rn((xr.x - __half2float(h0)) * 2048.0f),
                                    __float2half_rn((xr.y - __half2float(h1)) * 2048.0f));
        usm[hb + PLANE + 1] = pack2(__float2half_rn((xr.z - __half2float(h2)) * 2048.0f),
                                    __float2half_rn((xr.w - __half2float(h3)) * 2048.0f));
    };
    if (isld) store_x(0);
    __syncthreads();

    const bool evengid = !(gid & 1);
    const int  n0 = 2 * tig;                  // batch rows n0, n0+1 (0..7)
    const int  scr = pair * 32 + lane;        // scratch lane slot (conflict-free)

    int p = 0;
    for (int t = 0; t < TSTEPS; t++) {
        if (isld && t + 1 < TSTEPS) xr = xp4[(t + 1) * 7];   // prefetch

        // 3 independent accumulation chains, depth 3 each
        float accA[4], accB1[4], accB2[4];
        accA[0] = bias0; accA[1] = bias0; accA[2] = bias1; accA[3] = bias1;
#pragma unroll
        for (int r = 0; r < 4; r++) { accB1[r] = 0.0f; accB2[r] = 0.0f; }

        const int hbase = (p * 2) * PLANE + gid * S;   // n-row = gid (0..7)
        const int lbase = hbase + PLANE;
#pragma unroll
        for (int c = 0; c < 3; c++) {
            int cc = c0 + c;
            uint32_t bh[2], bl[2];
            bh[0] = usm[hbase + cc * 8 + tig];
            bh[1] = usm[hbase + cc * 8 + tig + 4];
            bl[0] = usm[lbase + cc * 8 + tig];
            bl[1] = usm[lbase + cc * 8 + tig + 4];
            mma16(accA,  whi[c], bh);
            mma16(accB1, wlo[c], bh);
            mma16(accB2, whi[c], bl);
        }

        // per-warp partial: accA + (accB1+accB2)/2048
        float pr[4];
#pragma unroll
        for (int r = 0; r < 4; r++)
            pr[r] = accA[r] + (accB1[r] + accB2[r]) * INV2048;

        const int q = p ^ 1;
        if (sub) {
            // publish partials, then free to prefetch-store x
#pragma unroll
            for (int r = 0; r < 4; r++)
                sm[SCRATCH + r * 128 + scr] = pr[r];
            asm volatile("bar.sync %0, 64;" :: "r"(pair + 1));
            if (isld && t + 1 < TSTEPS) store_x(q);
        } else {
            asm volatile("bar.sync %0, 64;" :: "r"(pair + 1));
#pragma unroll
            for (int r = 0; r < 4; r++)
                pr[r] += sm[SCRATCH + r * 128 + scr];

            float v0 = fast_tanh(pr[0]);
            float v1 = fast_tanh(pr[1]);
            float v2 = fast_tanh(pr[2]);
            float v3 = fast_tanh(pr[3]);

            // j-pair exchange across lane^4 (same tig, flips gid parity)
            float s0 = evengid ? v2 : v0;
            float s1 = evengid ? v3 : v1;
            float r0 = __shfl_xor_sync(0xffffffffu, s0, 4);
            float r1 = __shfl_xor_sync(0xffffffffu, s1, 4);

            int kp = evengid ? ((m0 + gid) >> 1) : ((m0 + gid + 7) >> 1);
            float a0 = evengid ? v0 : r0;   // lower-j value, row n0
            float c0v = evengid ? r0 : v2;  // upper-j value, row n0
            float a1 = evengid ? v1 : r1;   // row n0+1
            float c1v = evengid ? r1 : v3;

            __half ha0 = __float2half_rn(a0), hc0 = __float2half_rn(c0v);
            __half ha1 = __float2half_rn(a1), hc1 = __float2half_rn(c1v);
            int whb = (q * 2) * PLANE + n0 * S + kp;
            usm[whb]     = pack2(ha0, hc0);
            usm[whb + S] = pack2(ha1, hc1);
            usm[whb + PLANE]     = pack2(__float2half_rn((a0 - __half2float(ha0)) * 2048.0f),
                                         __float2half_rn((c0v - __half2float(hc0)) * 2048.0f));
            usm[whb + PLANE + S] = pack2(__float2half_rn((a1 - __half2float(ha1)) * 2048.0f),
                                         __float2half_rn((c1v - __half2float(hc1)) * 2048.0f));
        }

        __syncthreads();
        p = q;
    }

    // ---- Output projection: stage W_out past scratch ----
    for (int idx = tid; idx < OUT_DIM * HID; idx += NTHREADS) sm[WOUT_OFF + idx] = W_out[idx];
    if (tid < OUT_DIM) sm[WOUT_OFF + OUT_DIM * HID + tid] = b_out[tid];
    __syncthreads();

    const int hb = (p * 2) * PLANE;
    for (int idx = tid; idx < BTILE * OUT_DIM; idx += NTHREADS) {
        int n = idx / OUT_DIM, o = idx % OUT_DIM;
        float s = sm[WOUT_OFF + OUT_DIM * HID + o];
#pragma unroll 8
        for (int jp = 0; jp < HID / 2; jp++) {
            __half2 hh = *reinterpret_cast<const __half2*>(&usm[hb + n * S + jp]);
            __half2 ll = *reinterpret_cast<const __half2*>(&usm[hb + PLANE + n * S + jp]);
            float2 fh = __half22float2(hh), fl = __half22float2(ll);
            s += (fh.x + fl.x * INV2048) * sm[WOUT_OFF + o * HID + 2 * jp]
               + (fh.y + fl.y * INV2048) * sm[WOUT_OFF + o * HID + 2 * jp + 1];
        }
        out[(size_t)(b0 + n) * OUT_DIM + o] = s;
    }
}

extern "C" void kernel_launch(void* const* d_in, const int* in_sizes, int n_in,
                              void* d_out, int out_size)
{
    const float* x     = (const float*)d_in[0];
    const float* W_ih  = (const float*)d_in[1];
    const float* W_hh  = (const float*)d_in[2];
    const float* b_ih  = (const float*)d_in[3];
    const float* b_hh  = (const float*)d_in[4];
    const float* W_out = (const float*)d_in[5];
    const float* b_out = (const float*)d_in[6];
    float* out = (float*)d_out;

    cudaFuncSetAttribute(rnn_ks_kernel,
                         cudaFuncAttributeMaxDynamicSharedMemorySize, SMEM_BYTES);

    dim3 grid(BATCH / BTILE);   // 512 CTAs, 8 persistent batch rows each
    dim3 block(NTHREADS);       // 8 warps: 4 m-pairs x 2 k-halves
    rnn_ks_kernel<<<grid, block, SMEM_BYTES>>>(x, W_ih, W_hh, b_ih, b_hh,
                                               W_out, b_out, out);
}

// round 11
// speedup vs baseline: 1.0631x; 1.0631x over previous
#include <cuda_runtime.h>
#include <cuda_fp16.h>
#include <cstdint>

// RNN: h_t = tanh([h_{t-1} | x_t] @ [W_hh | W_ih]^T + b), out = h_T @ W_out^T + b_out
// fp16-split 3-pass mma.m16n8k16; W = W_hi + W_lo/2048, state likewise.
// Round 11: R9 config (BTILE=8, 512 CTAs, 4 warps x m=16) + INTERLEAVED hi/lo state
// layout: word 2k = hi of k-pair, word 2k+1 = lo. Enables LDS.64 fragment loads,
// STS.64 h writeback, STS.128 x staging. Row stride 100 (== 4 mod 32): 2-phase-
// optimal banking for all accesses.

#define BATCH    4096
#define TSTEPS   512
#define IN_DIM   28
#define HID      64
#define OUT_DIM  10
#define KCOMB    96           // 64 h + 28 x + 4 pad
#define CHUNKS   6            // KCOMB / 16
#define BTILE    8
#define NTHREADS 128          // 4 warps, each m=16, n=8
#define S2       100          // words per n-row (96 data + 4 pad); 100 % 32 == 4
#define BUF      (BTILE * S2) // 800 words per buffer (hi/lo interleaved)
#define STATE_WORDS (2 * BUF)           // 1600 (double buffer)
#define BIAS_OFF (HID * KCOMB)          // 6144 (stage area, overlaid by state later)
#define SMEM_WORDS (BIAS_OFF + HID)     // 6208
#define SMEM_BYTES (SMEM_WORDS * 4)     // 24832 B
#define WOUT_OFF 1664                   // W_out stage for epilogue (past state)

#define INV2048  4.8828125e-4f

__device__ __forceinline__ float fast_tanh(float v) {
    float e = __expf(2.0f * v);
    return 1.0f - __fdividef(2.0f, e + 1.0f);
}

__device__ __forceinline__ uint32_t pack2(__half lo, __half hi) {
    __half2 h = __halves2half2(lo, hi);
    return *reinterpret_cast<uint32_t*>(&h);
}

__device__ __forceinline__ void mma16(float* d, const uint32_t* a, const uint32_t* b) {
    asm volatile(
        "mma.sync.aligned.m16n8k16.row.col.f32.f16.f16.f32 "
        "{%0,%1,%2,%3}, {%4,%5,%6,%7}, {%8,%9}, {%0,%1,%2,%3};"
        : "+f"(d[0]), "+f"(d[1]), "+f"(d[2]), "+f"(d[3])
        : "r"(a[0]), "r"(a[1]), "r"(a[2]), "r"(a[3]), "r"(b[0]), "r"(b[1]));
}

__global__ void __launch_bounds__(NTHREADS, 4)
rnn_v64_kernel(const float* __restrict__ x,
               const float* __restrict__ W_ih,
               const float* __restrict__ W_hh,
               const float* __restrict__ b_ih,
               const float* __restrict__ b_hh,
               const float* __restrict__ W_out,
               const float* __restrict__ b_out,
               float* __restrict__ out)
{
    extern __shared__ float sm[];
    uint32_t* usm = (uint32_t*)sm;

    const int tid  = threadIdx.x;
    const int b0   = blockIdx.x * BTILE;
    const int lane = tid & 31;
    const int mg   = tid >> 5;     // warp id = m-group: W rows [mg*16, mg*16+16)
    const int gid  = lane >> 2;
    const int tig  = lane & 3;
    const int m0   = mg * 16;

    // ---- Stage combined weight Wc[64][96] fp32 at sm[0..6144) + bias ----
    for (int idx = tid; idx < HID * KCOMB; idx += NTHREADS) {
        int j = idx / KCOMB, k = idx % KCOMB;
        float v = 0.0f;
        if (k < HID)               v = W_hh[j * HID + k];
        else if (k < HID + IN_DIM) v = W_ih[j * IN_DIM + (k - HID)];
        sm[idx] = v;
    }
    if (tid < HID) sm[BIAS_OFF + tid] = b_ih[tid] + b_hh[tid];
    __syncthreads();

    // ---- W fragments (A operand, one m16k16 tile per warp), hi + scaled-lo fp16 ----
    uint32_t whi[CHUNKS][4], wlo[CHUNKS][4];
#pragma unroll
    for (int c = 0; c < CHUNKS; c++) {
#pragma unroll
        for (int r = 0; r < 4; r++) {
            int row = m0 + gid + (r & 1) * 8;
            int k0  = c * 16 + 2 * tig + (r >> 1) * 8;
            float va = sm[row * KCOMB + k0];
            float vb = sm[row * KCOMB + k0 + 1];
            __half ha = __float2half_rn(va), hb = __float2half_rn(vb);
            whi[c][r] = pack2(ha, hb);
            wlo[c][r] = pack2(
                __float2half_rn((va - __half2float(ha)) * 2048.0f),
                __float2half_rn((vb - __half2float(hb)) * 2048.0f));
        }
    }
    const float bias0 = sm[BIAS_OFF + m0 + gid];
    const float bias1 = sm[BIAS_OFF + m0 + gid + 8];
    __syncthreads();   // frag reads done; stage area reused as state

    // ---- Zero state double-buffers (h=0, lo=0, pads 0) ----
    for (int idx = tid; idx < STATE_WORDS; idx += NTHREADS) sm[idx] = 0.0f;

    // ---- x loader: 56 threads, one float4 (4 k-values of one row) per step ----
    const bool isld = tid < 56;
    const int  xn = isld ? tid / 7 : 0;       // row 0..7
    const int  xq = isld ? tid % 7 : 0;
    const float4* xp4 = (const float4*)(x + (size_t)(b0 + xn) * TSTEPS * IN_DIM) + xq;

    float4 xr = make_float4(0, 0, 0, 0);
    if (isld) xr = xp4[0];                    // t = 0
    __syncthreads();                          // zero-fill visible

    // x k-values 4xq.. occupy k-pairs w=32+2xq, 32+2xq+1 -> interleaved words
    // [2w, 2w+1, 2w+2, 2w+3] = [hi01, lo01, hi23, lo23]: one STS.128 (16B aligned).
    auto store_x = [&](int p) {
        int wbase = p * BUF + xn * S2 + 64 + 4 * xq;
        __half h0 = __float2half_rn(xr.x), h1 = __float2half_rn(xr.y);
        __half h2 = __float2half_rn(xr.z), h3 = __float2half_rn(xr.w);
        uint4 v;
        v.x = pack2(h0, h1);
        v.y = pack2(__float2half_rn((xr.x - __half2float(h0)) * 2048.0f),
                    __float2half_rn((xr.y - __half2float(h1)) * 2048.0f));
        v.z = pack2(h2, h3);
        v.w = pack2(__float2half_rn((xr.z - __half2float(h2)) * 2048.0f),
                    __float2half_rn((xr.w - __half2float(h3)) * 2048.0f));
        *reinterpret_cast<uint4*>(&usm[wbase]) = v;
    };
    if (isld) store_x(0);
    __syncthreads();

    const bool evengid = !(gid & 1);
    const int  n0 = 2 * tig;                  // batch rows n0, n0+1 (0..7)

    int p = 0;
    for (int t = 0; t < TSTEPS; t++) {
        if (isld && t + 1 < TSTEPS) xr = xp4[(t + 1) * 7];   // prefetch

        // 3 independent accumulation chains, depth 6 each
        float accA[4], accB1[4], accB2[4];
        accA[0] = bias0; accA[1] = bias0; accA[2] = bias1; accA[3] = bias1;
#pragma unroll
        for (int r = 0; r < 4; r++) { accB1[r] = 0.0f; accB2[r] = 0.0f; }

        const int hbase = p * BUF + gid * S2;   // n-row = gid (0..7)
#pragma unroll
        for (int c = 0; c < CHUNKS; c++) {
            // LDS.64: (hi, lo) of k-pair word c*8+tig and c*8+tig+4
            uint2 d0 = *reinterpret_cast<const uint2*>(&usm[hbase + 2 * (c * 8 + tig)]);
            uint2 d1 = *reinterpret_cast<const uint2*>(&usm[hbase + 2 * (c * 8 + tig + 4)]);
            uint32_t bh[2] = { d0.x, d1.x };
            uint32_t bl[2] = { d0.y, d1.y };
            mma16(accA,  whi[c], bh);
            mma16(accB1, wlo[c], bh);
            mma16(accB2, whi[c], bl);
        }

        // tanh -> shfl-pair -> fp16-split -> STS.64 into buffer q
        const int q = p ^ 1;
        float v0 = fast_tanh(accA[0] + (accB1[0] + accB2[0]) * INV2048);
        float v1 = fast_tanh(accA[1] + (accB1[1] + accB2[1]) * INV2048);
        float v2 = fast_tanh(accA[2] + (accB1[2] + accB2[2]) * INV2048);
        float v3 = fast_tanh(accA[3] + (accB1[3] + accB2[3]) * INV2048);

        // exchange across j-pair partner (lane ^ 4, same tig)
        float s0 = evengid ? v2 : v0;
        float s1 = evengid ? v3 : v1;
        float r0 = __shfl_xor_sync(0xffffffffu, s0, 4);
        float r1 = __shfl_xor_sync(0xffffffffu, s1, 4);

        {
            int kp = evengid ? ((m0 + gid) >> 1) : ((m0 + gid + 7) >> 1);
            float a0 = evengid ? v0 : r0;   // lower-j value, row n0
            float c0 = evengid ? r0 : v2;   // upper-j value, row n0
            float a1 = evengid ? v1 : r1;   // row n0+1
            float c1 = evengid ? r1 : v3;

            __half ha0 = __float2half_rn(a0), hc0 = __float2half_rn(c0);
            __half ha1 = __float2half_rn(a1), hc1 = __float2half_rn(c1);
            int wb = q * BUF + n0 * S2 + 2 * kp;
            uint2 w0, w1;
            w0.x = pack2(ha0, hc0);
            w0.y = pack2(__float2half_rn((a0 - __half2float(ha0)) * 2048.0f),
                         __float2half_rn((c0 - __half2float(hc0)) * 2048.0f));
            w1.x = pack2(ha1, hc1);
            w1.y = pack2(__float2half_rn((a1 - __half2float(ha1)) * 2048.0f),
                         __float2half_rn((c1 - __half2float(hc1)) * 2048.0f));
            *reinterpret_cast<uint2*>(&usm[wb])      = w0;   // row n0
            *reinterpret_cast<uint2*>(&usm[wb + S2]) = w1;   // row n0+1
        }

        if (isld && t + 1 < TSTEPS) store_x(q);
        __syncthreads();
        p = q;
    }

    // ---- Output projection: stage W_out past the state region ----
    for (int idx = tid; idx < OUT_DIM * HID; idx += NTHREADS) sm[WOUT_OFF + idx] = W_out[idx];
    if (tid < OUT_DIM) sm[WOUT_OFF + OUT_DIM * HID + tid] = b_out[tid];
    __syncthreads();

    const int hb = p * BUF;
    for (int idx = tid; idx < BTILE * OUT_DIM; idx += NTHREADS) {
        int n = idx / OUT_DIM, o = idx % OUT_DIM;
        float s = sm[WOUT_OFF + OUT_DIM * HID + o];
#pragma unroll 8
        for (int jp = 0; jp < HID / 2; jp++) {
            uint2 d = *reinterpret_cast<const uint2*>(&usm[hb + n * S2 + 2 * jp]);
            float2 fh = __half22float2(*reinterpret_cast<__half2*>(&d.x));
            float2 fl = __half22float2(*reinterpret_cast<__half2*>(&d.y));
            s += (fh.x + fl.x * INV2048) * sm[WOUT_OFF + o * HID + 2 * jp]
               + (fh.y + fl.y * INV2048) * sm[WOUT_OFF + o * HID + 2 * jp + 1];
        }
        out[(size_t)(b0 + n) * OUT_DIM + o] = s;
    }
}

extern "C" void kernel_launch(void* const* d_in, const int* in_sizes, int n_in,
                              void* d_out, int out_size)
{
    const float* x     = (const float*)d_in[0];
    const float* W_ih  = (const float*)d_in[1];
    const float* W_hh  = (const float*)d_in[2];
    const float* b_ih  = (const float*)d_in[3];
    const float* b_hh  = (const float*)d_in[4];
    const float* W_out = (const float*)d_in[5];
    const float* b_out = (const float*)d_in[6];
    float* out = (float*)d_out;

    cudaFuncSetAttribute(rnn_v64_kernel,
                         cudaFuncAttributeMaxDynamicSharedMemorySize, SMEM_BYTES);

    dim3 grid(BATCH / BTILE);   // 512 CTAs, 8 persistent batch rows each
    dim3 block(NTHREADS);       // 4 warps, each m=16
    rnn_v64_kernel<<<grid, block, SMEM_BYTES>>>(x, W_ih, W_hh, b_ih, b_hh,
                                                W_out, b_out, out);
}

// round 12
// speedup vs baseline: 1.2575x; 1.1829x over previous
#include <cuda_runtime.h>
#include <cuda_fp16.h>
#include <cstdint>

// RNN: h_t = tanh([h_{t-1} | x_t] @ [W_hh | W_ih]^T + b), out = h_T @ W_out^T + b_out
// Round 12: W kept fp16-split (W_hi + W_lo/2048, both passes), state stored fp16 ONLY.
//   acc = W_hi*s + W_lo*s/2048;  h stored as fp16 (rounding error ~2^-12, contractive
//   recurrence -> steady-state output error ~1e-4 << 1e-3 gate).
// R9 shape: BTILE=8, 512 CTAs, 4 warps x m=16. 12 mma + 12 LDS per warp-step,
// epilogue = tanh + shfl + 2 F2FP + 2 STS.

#define BATCH    4096
#define TSTEPS   512
#define IN_DIM   28
#define HID      64
#define OUT_DIM  10
#define KCOMB    96           // 64 h + 28 x + 4 pad (fp16 -> 48 words)
#define CHUNKS   6            // KCOMB / 16
#define BTILE    8
#define NTHREADS 128          // 4 warps, each m=16, n=8
#define S        68           // words per n-row (48 data + pad); 68 % 32 == 4 -> conflict-free
#define PLANE    (BTILE * S)  // 544 words: one buffer (hi only)
#define STATE_WORDS (2 * PLANE)         // 1088 (double buffer)
#define BIAS_OFF (HID * KCOMB)          // 6144 (stage area, overlaid by state later)
#define SMEM_WORDS (BIAS_OFF + HID)     // 6208
#define SMEM_BYTES (SMEM_WORDS * 4)     // 24832 B
#define WOUT_OFF 1152                   // W_out stage for epilogue (past state)

#define INV2048  4.8828125e-4f

__device__ __forceinline__ float fast_tanh(float v) {
    float e = __expf(2.0f * v);
    return 1.0f - __fdividef(2.0f, e + 1.0f);
}

__device__ __forceinline__ uint32_t pack2(__half lo, __half hi) {
    __half2 h = __halves2half2(lo, hi);
    return *reinterpret_cast<uint32_t*>(&h);
}

__device__ __forceinline__ uint32_t packf2(float a, float b) {
    __half2 h = __floats2half2_rn(a, b);    // one F2FP
    return *reinterpret_cast<uint32_t*>(&h);
}

__device__ __forceinline__ void mma16(float* d, const uint32_t* a, const uint32_t* b) {
    asm volatile(
        "mma.sync.aligned.m16n8k16.row.col.f32.f16.f16.f32 "
        "{%0,%1,%2,%3}, {%4,%5,%6,%7}, {%8,%9}, {%0,%1,%2,%3};"
        : "+f"(d[0]), "+f"(d[1]), "+f"(d[2]), "+f"(d[3])
        : "r"(a[0]), "r"(a[1]), "r"(a[2]), "r"(a[3]), "r"(b[0]), "r"(b[1]));
}

__global__ void __launch_bounds__(NTHREADS, 4)
rnn_2p_kernel(const float* __restrict__ x,
              const float* __restrict__ W_ih,
              const float* __restrict__ W_hh,
              const float* __restrict__ b_ih,
              const float* __restrict__ b_hh,
              const float* __restrict__ W_out,
              const float* __restrict__ b_out,
              float* __restrict__ out)
{
    extern __shared__ float sm[];
    uint32_t* usm = (uint32_t*)sm;

    const int tid  = threadIdx.x;
    const int b0   = blockIdx.x * BTILE;
    const int lane = tid & 31;
    const int mg   = tid >> 5;     // warp id = m-group: W rows [mg*16, mg*16+16)
    const int gid  = lane >> 2;
    const int tig  = lane & 3;
    const int m0   = mg * 16;

    // ---- Stage combined weight Wc[64][96] fp32 at sm[0..6144) + bias ----
    for (int idx = tid; idx < HID * KCOMB; idx += NTHREADS) {
        int j = idx / KCOMB, k = idx % KCOMB;
        float v = 0.0f;
        if (k < HID)               v = W_hh[j * HID + k];
        else if (k < HID + IN_DIM) v = W_ih[j * IN_DIM + (k - HID)];
        sm[idx] = v;
    }
    if (tid < HID) sm[BIAS_OFF + tid] = b_ih[tid] + b_hh[tid];
    __syncthreads();

    // ---- W fragments (A operand, one m16k16 tile per warp), hi + scaled-lo fp16 ----
    uint32_t whi[CHUNKS][4], wlo[CHUNKS][4];
#pragma unroll
    for (int c = 0; c < CHUNKS; c++) {
#pragma unroll
        for (int r = 0; r < 4; r++) {
            int row = m0 + gid + (r & 1) * 8;
            int k0  = c * 16 + 2 * tig + (r >> 1) * 8;
            float va = sm[row * KCOMB + k0];
            float vb = sm[row * KCOMB + k0 + 1];
            __half ha = __float2half_rn(va), hb = __float2half_rn(vb);
            whi[c][r] = pack2(ha, hb);
            wlo[c][r] = pack2(
                __float2half_rn((va - __half2float(ha)) * 2048.0f),
                __float2half_rn((vb - __half2float(hb)) * 2048.0f));
        }
    }
    const float bias0 = sm[BIAS_OFF + m0 + gid];
    const float bias1 = sm[BIAS_OFF + m0 + gid + 8];
    __syncthreads();   // frag reads done; stage area reused as state

    // ---- Zero state double-buffers (h=0, pads 0) ----
    for (int idx = tid; idx < STATE_WORDS; idx += NTHREADS) sm[idx] = 0.0f;

    // ---- x loader: 56 threads, one float4 (4 k-values of one row) per step ----
    const bool isld = tid < 56;
    const int  xn = isld ? tid / 7 : 0;       // row 0..7
    const int  xq = isld ? tid % 7 : 0;
    const float4* xp4 = (const float4*)(x + (size_t)(b0 + xn) * TSTEPS * IN_DIM) + xq;

    float4 xr = make_float4(0, 0, 0, 0);
    if (isld) xr = xp4[0];                    // t = 0
    __syncthreads();                          // zero-fill visible

    // x k-values 4xq..4xq+3 -> words 32+2xq, 32+2xq+1 (hi only): one STS.64
    auto store_x = [&](int p) {
        int wb = p * PLANE + xn * S + 32 + 2 * xq;
        uint2 v;
        v.x = packf2(xr.x, xr.y);
        v.y = packf2(xr.z, xr.w);
        *reinterpret_cast<uint2*>(&usm[wb]) = v;
    };
    if (isld) store_x(0);
    __syncthreads();

    const bool evengid = !(gid & 1);
    const int  n0 = 2 * tig;                  // batch rows n0, n0+1 (0..7)

    int p = 0;
    for (int t = 0; t < TSTEPS; t++) {
        if (isld && t + 1 < TSTEPS) xr = xp4[(t + 1) * 7];   // prefetch

        // 2 independent accumulation chains, depth 6 each
        float accA[4], accB[4];
        accA[0] = bias0; accA[1] = bias0; accA[2] = bias1; accA[3] = bias1;
        accB[0] = 0.0f; accB[1] = 0.0f; accB[2] = 0.0f; accB[3] = 0.0f;

        const int hbase = p * PLANE + gid * S;   // n-row = gid (0..7)
#pragma unroll
        for (int c = 0; c < CHUNKS; c++) {
            uint32_t b[2];
            b[0] = usm[hbase + c * 8 + tig];
            b[1] = usm[hbase + c * 8 + tig + 4];
            mma16(accA, whi[c], b);
            mma16(accB, wlo[c], b);
        }

        // tanh -> shfl-pair -> fp16 -> 2x STS.32 into buffer q
        const int q = p ^ 1;
        float v0 = fast_tanh(accA[0] + accB[0] * INV2048);
        float v1 = fast_tanh(accA[1] + accB[1] * INV2048);
        float v2 = fast_tanh(accA[2] + accB[2] * INV2048);
        float v3 = fast_tanh(accA[3] + accB[3] * INV2048);

        // exchange across j-pair partner (lane ^ 4, same tig)
        float s0 = evengid ? v2 : v0;
        float s1 = evengid ? v3 : v1;
        float r0 = __shfl_xor_sync(0xffffffffu, s0, 4);
        float r1 = __shfl_xor_sync(0xffffffffu, s1, 4);

        {
            int kp = evengid ? ((m0 + gid) >> 1) : ((m0 + gid + 7) >> 1);
            float a0 = evengid ? v0 : r0;   // lower-j value, row n0
            float c0 = evengid ? r0 : v2;   // upper-j value, row n0
            float a1 = evengid ? v1 : r1;   // row n0+1
            float c1 = evengid ? r1 : v3;

            int wb = q * PLANE + n0 * S + kp;
            usm[wb]     = packf2(a0, c0);   // row n0
            usm[wb + S] = packf2(a1, c1);   // row n0+1
        }

        if (isld && t + 1 < TSTEPS) store_x(q);
        __syncthreads();
        p = q;
    }

    // ---- Output projection: stage W_out past the state region ----
    for (int idx = tid; idx < OUT_DIM * HID; idx += NTHREADS) sm[WOUT_OFF + idx] = W_out[idx];
    if (tid < OUT_DIM) sm[WOUT_OFF + OUT_DIM * HID + tid] = b_out[tid];
    __syncthreads();

    const int hb = p * PLANE;
    for (int idx = tid; idx < BTILE * OUT_DIM; idx += NTHREADS) {
        int n = idx / OUT_DIM, o = idx % OUT_DIM;
        float s = sm[WOUT_OFF + OUT_DIM * HID + o];
#pragma unroll 8
        for (int jp = 0; jp < HID / 2; jp++) {
            __half2 hh = *reinterpret_cast<const __half2*>(&usm[hb + n * S + jp]);
            float2 fh = __half22float2(hh);
            s += fh.x * sm[WOUT_OFF + o * HID + 2 * jp]
               + fh.y * sm[WOUT_OFF + o * HID + 2 * jp + 1];
        }
        out[(size_t)(b0 + n) * OUT_DIM + o] = s;
    }
}

extern "C" void kernel_launch(void* const* d_in, const int* in_sizes, int n_in,
                              void* d_out, int out_size)
{
    const float* x     = (const float*)d_in[0];
    const float* W_ih  = (const float*)d_in[1];
    const float* W_hh  = (const float*)d_in[2];
    const float* b_ih  = (const float*)d_in[3];
    const float* b_hh  = (const float*)d_in[4];
    const float* W_out = (const float*)d_in[5];
    const float* b_out = (const float*)d_in[6];
    float* out = (float*)d_out;

    cudaFuncSetAttribute(rnn_2p_kernel,
                         cudaFuncAttributeMaxDynamicSharedMemorySize, SMEM_BYTES);

    dim3 grid(BATCH / BTILE);   // 512 CTAs, 8 persistent batch rows each
    dim3 block(NTHREADS);       // 4 warps, each m=16
    rnn_2p_kernel<<<grid, block, SMEM_BYTES>>>(x, W_ih, W_hh, b_ih, b_hh,
                                               W_out, b_out, out);
}

// round 13
// speedup vs baseline: 1.3193x; 1.0491x over previous
#include <cuda_runtime.h>
#include <cuda_fp16.h>
#include <cstdint>

// RNN: h_t = tanh([h_{t-1} | x_t] @ [W_hh | W_ih]^T + b), out = h_T @ W_out^T + b_out
// Round 13: R12 base (W fp16-split 2-pass, state fp16-only, BTILE=8, 512 CTAs,
// 4 warps x m=16) + serial-path cuts:
//   - 2-step-deep x prefetch (xr0/xr1) -> DRAM latency off the barrier path
//   - tanh.approx.f32 (MUFU.TANH, 1 op vs ~6)
//   - direct STS.16 h writeback (no shfl pair exchange)
//   - accB split into 2 depth-3 mma chains

#define BATCH    4096
#define TSTEPS   512
#define IN_DIM   28
#define HID      64
#define OUT_DIM  10
#define KCOMB    96           // 64 h + 28 x + 4 pad (fp16 -> 48 words)
#define CHUNKS   6            // KCOMB / 16
#define BTILE    8
#define NTHREADS 128          // 4 warps, each m=16, n=8
#define S        68           // words per n-row; 68 % 32 == 4 -> conflict-free maps
#define PLANE    (BTILE * S)  // 544 words: one buffer (hi only)
#define STATE_WORDS (2 * PLANE)         // 1088 (double buffer)
#define BIAS_OFF (HID * KCOMB)          // 6144 (stage area, overlaid by state later)
#define SMEM_WORDS (BIAS_OFF + HID)     // 6208
#define SMEM_BYTES (SMEM_WORDS * 4)     // 24832 B
#define WOUT_OFF 1152                   // W_out stage for epilogue (past state)

#define INV2048  4.8828125e-4f

__device__ __forceinline__ float tanh_hw(float v) {
    float r;
    asm("tanh.approx.f32 %0, %1;" : "=f"(r) : "f"(v));   // MUFU.TANH
    return r;
}

__device__ __forceinline__ uint32_t pack2(__half lo, __half hi) {
    __half2 h = __halves2half2(lo, hi);
    return *reinterpret_cast<uint32_t*>(&h);
}

__device__ __forceinline__ uint32_t packf2(float a, float b) {
    __half2 h = __floats2half2_rn(a, b);
    return *reinterpret_cast<uint32_t*>(&h);
}

__device__ __forceinline__ void mma16(float* d, const uint32_t* a, const uint32_t* b) {
    asm volatile(
        "mma.sync.aligned.m16n8k16.row.col.f32.f16.f16.f32 "
        "{%0,%1,%2,%3}, {%4,%5,%6,%7}, {%8,%9}, {%0,%1,%2,%3};"
        : "+f"(d[0]), "+f"(d[1]), "+f"(d[2]), "+f"(d[3])
        : "r"(a[0]), "r"(a[1]), "r"(a[2]), "r"(a[3]), "r"(b[0]), "r"(b[1]));
}

__global__ void __launch_bounds__(NTHREADS, 4)
rnn_r13_kernel(const float* __restrict__ x,
               const float* __restrict__ W_ih,
               const float* __restrict__ W_hh,
               const float* __restrict__ b_ih,
               const float* __restrict__ b_hh,
               const float* __restrict__ W_out,
               const float* __restrict__ b_out,
               float* __restrict__ out)
{
    extern __shared__ float sm[];
    uint32_t* usm = (uint32_t*)sm;
    __half*   hsm = (__half*)sm;

    const int tid  = threadIdx.x;
    const int b0   = blockIdx.x * BTILE;
    const int lane = tid & 31;
    const int mg   = tid >> 5;     // warp id = m-group: W rows [mg*16, mg*16+16)
    const int gid  = lane >> 2;
    const int tig  = lane & 3;
    const int m0   = mg * 16;

    // ---- Stage combined weight Wc[64][96] fp32 at sm[0..6144) + bias ----
    for (int idx = tid; idx < HID * KCOMB; idx += NTHREADS) {
        int j = idx / KCOMB, k = idx % KCOMB;
        float v = 0.0f;
        if (k < HID)               v = W_hh[j * HID + k];
        else if (k < HID + IN_DIM) v = W_ih[j * IN_DIM + (k - HID)];
        sm[idx] = v;
    }
    if (tid < HID) sm[BIAS_OFF + tid] = b_ih[tid] + b_hh[tid];
    __syncthreads();

    // ---- W fragments (A operand, one m16k16 tile per warp), hi + scaled-lo fp16 ----
    uint32_t whi[CHUNKS][4], wlo[CHUNKS][4];
#pragma unroll
    for (int c = 0; c < CHUNKS; c++) {
#pragma unroll
        for (int r = 0; r < 4; r++) {
            int row = m0 + gid + (r & 1) * 8;
            int k0  = c * 16 + 2 * tig + (r >> 1) * 8;
            float va = sm[row * KCOMB + k0];
            float vb = sm[row * KCOMB + k0 + 1];
            __half ha = __float2half_rn(va), hb = __float2half_rn(vb);
            whi[c][r] = pack2(ha, hb);
            wlo[c][r] = pack2(
                __float2half_rn((va - __half2float(ha)) * 2048.0f),
                __float2half_rn((vb - __half2float(hb)) * 2048.0f));
        }
    }
    const float bias0 = sm[BIAS_OFF + m0 + gid];
    const float bias1 = sm[BIAS_OFF + m0 + gid + 8];
    __syncthreads();   // frag reads done; stage area reused as state

    // ---- Zero state double-buffers (h=0, pads 0) ----
    for (int idx = tid; idx < STATE_WORDS; idx += NTHREADS) sm[idx] = 0.0f;

    // ---- x loader: 56 threads, one float4 per step, 2-step-deep pipeline ----
    const bool isld = tid < 56;
    const int  xn = isld ? tid / 7 : 0;       // row 0..7
    const int  xq = isld ? tid % 7 : 0;
    const float4* xp4 = (const float4*)(x + (size_t)(b0 + xn) * TSTEPS * IN_DIM) + xq;

    float4 xr0 = make_float4(0, 0, 0, 0);     // x(t+1), stored at end of step t
    float4 xr1 = make_float4(0, 0, 0, 0);     // x(t+2), in flight

    auto store_xv = [&](int p, const float4& v) {
        int wb = p * PLANE + xn * S + 32 + 2 * xq;
        uint2 w;
        w.x = packf2(v.x, v.y);
        w.y = packf2(v.z, v.w);
        *reinterpret_cast<uint2*>(&usm[wb]) = w;
    };

    __syncthreads();                           // zero-fill visible
    if (isld) {
        float4 v0 = xp4[0];                    // x(0)
        store_xv(0, v0);
        xr0 = xp4[7];                          // x(1)
    }
    __syncthreads();

    const int n0 = 2 * tig;                    // batch rows n0, n0+1 (0..7)

    int p = 0;
    for (int t = 0; t < TSTEPS; t++) {
        // issue LDG for x(t+2): ~2-step window before consumption
        if (isld && t + 2 < TSTEPS) xr1 = xp4[(t + 2) * 7];

        // accA depth 6; accB split in two depth-3 chains
        float accA[4], accB1[4], accB2[4];
        accA[0] = bias0; accA[1] = bias0; accA[2] = bias1; accA[3] = bias1;
#pragma unroll
        for (int r = 0; r < 4; r++) { accB1[r] = 0.0f; accB2[r] = 0.0f; }

        const int hbase = p * PLANE + gid * S;   // n-row = gid (0..7)
#pragma unroll
        for (int c = 0; c < CHUNKS; c++) {
            uint32_t b[2];
            b[0] = usm[hbase + c * 8 + tig];
            b[1] = usm[hbase + c * 8 + tig + 4];
            mma16(accA, whi[c], b);
            if (c & 1) mma16(accB1, wlo[c], b);
            else       mma16(accB2, wlo[c], b);
        }

        // tanh.approx -> direct half stores (no shfl)
        const int q = p ^ 1;
        float v0 = tanh_hw(accA[0] + (accB1[0] + accB2[0]) * INV2048);
        float v1 = tanh_hw(accA[1] + (accB1[1] + accB2[1]) * INV2048);
        float v2 = tanh_hw(accA[2] + (accB1[2] + accB2[2]) * INV2048);
        float v3 = tanh_hw(accA[3] + (accB1[3] + accB2[3]) * INV2048);

        {
            // halfword index = 2*(buffer word base) + j
            int hb0 = (q * PLANE + n0 * S) * 2;        // row n0
            int hb1 = hb0 + 2 * S;                     // row n0+1
            int jA = m0 + gid, jB = jA + 8;
            hsm[hb0 + jA] = __float2half_rn(v0);
            hsm[hb1 + jA] = __float2half_rn(v1);
            hsm[hb0 + jB] = __float2half_rn(v2);
            hsm[hb1 + jB] = __float2half_rn(v3);
        }

        if (isld && t + 1 < TSTEPS) store_xv(q, xr0);
        xr0 = xr1;
        __syncthreads();
        p = q;
    }

    // ---- Output projection: stage W_out past the state region ----
    for (int idx = tid; idx < OUT_DIM * HID; idx += NTHREADS) sm[WOUT_OFF + idx] = W_out[idx];
    if (tid < OUT_DIM) sm[WOUT_OFF + OUT_DIM * HID + tid] = b_out[tid];
    __syncthreads();

    const int hb = p * PLANE;
    for (int idx = tid; idx < BTILE * OUT_DIM; idx += NTHREADS) {
        int n = idx / OUT_DIM, o = idx % OUT_DIM;
        float s = sm[WOUT_OFF + OUT_DIM * HID + o];
#pragma unroll 8
        for (int jp = 0; jp < HID / 2; jp++) {
            __half2 hh = *reinterpret_cast<const __half2*>(&usm[hb + n * S + jp]);
            float2 fh = __half22float2(hh);
            s += fh.x * sm[WOUT_OFF + o * HID + 2 * jp]
               + fh.y * sm[WOUT_OFF + o * HID + 2 * jp + 1];
        }
        out[(size_t)(b0 + n) * OUT_DIM + o] = s;
    }
}

extern "C" void kernel_launch(void* const* d_in, const int* in_sizes, int n_in,
                              void* d_out, int out_size)
{
    const float* x     = (const float*)d_in[0];
    const float* W_ih  = (const float*)d_in[1];
    const float* W_hh  = (const float*)d_in[2];
    const float* b_ih  = (const float*)d_in[3];
    const float* b_hh  = (const float*)d_in[4];
    const float* W_out = (const float*)d_in[5];
    const float* b_out = (const float*)d_in[6];
    float* out = (float*)d_out;

    cudaFuncSetAttribute(rnn_r13_kernel,
                         cudaFuncAttributeMaxDynamicSharedMemorySize, SMEM_BYTES);

    dim3 grid(BATCH / BTILE);   // 512 CTAs, 8 persistent batch rows each
    dim3 block(NTHREADS);       // 4 warps, each m=16
    rnn_r13_kernel<<<grid, block, SMEM_BYTES>>>(x, W_ih, W_hh, b_ih, b_hh,
                                                W_out, b_out, out);
}

// round 14
// speedup vs baseline: 1.3348x; 1.0117x over previous
#include <cuda_runtime.h>
#include <cuda_fp16.h>
#include <cstdint>

// RNN: h_t = tanh([h_{t-1} | x_t] @ [W_hh | W_ih]^T + b), out = h_T @ W_out^T + b_out
// Round 14: R13 base (W fp16-split 2-pass, state fp16-only, BTILE=8, 512 CTAs,
// 4 warps x m=16, tanh.approx, direct STS.16 writeback, 2-deep x prefetch)
// + accA split into 3 independent chains of depth 2 (was 1x depth 6) to cut
// dependent-HMMA latency off the per-step critical path.

#define BATCH    4096
#define TSTEPS   512
#define IN_DIM   28
#define HID      64
#define OUT_DIM  10
#define KCOMB    96           // 64 h + 28 x + 4 pad (fp16 -> 48 words)
#define CHUNKS   6            // KCOMB / 16
#define BTILE    8
#define NTHREADS 128          // 4 warps, each m=16, n=8
#define S        68           // words per n-row; 68 % 32 == 4 -> conflict-free maps
#define PLANE    (BTILE * S)  // 544 words: one buffer (hi only)
#define STATE_WORDS (2 * PLANE)         // 1088 (double buffer)
#define BIAS_OFF (HID * KCOMB)          // 6144 (stage area, overlaid by state later)
#define SMEM_WORDS (BIAS_OFF + HID)     // 6208
#define SMEM_BYTES (SMEM_WORDS * 4)     // 24832 B
#define WOUT_OFF 1152                   // W_out stage for epilogue (past state)

#define INV2048  4.8828125e-4f

__device__ __forceinline__ float tanh_hw(float v) {
    float r;
    asm("tanh.approx.f32 %0, %1;" : "=f"(r) : "f"(v));   // MUFU.TANH
    return r;
}

__device__ __forceinline__ uint32_t pack2(__half lo, __half hi) {
    __half2 h = __halves2half2(lo, hi);
    return *reinterpret_cast<uint32_t*>(&h);
}

__device__ __forceinline__ uint32_t packf2(float a, float b) {
    __half2 h = __floats2half2_rn(a, b);
    return *reinterpret_cast<uint32_t*>(&h);
}

__device__ __forceinline__ void mma16(float* d, const uint32_t* a, const uint32_t* b) {
    asm volatile(
        "mma.sync.aligned.m16n8k16.row.col.f32.f16.f16.f32 "
        "{%0,%1,%2,%3}, {%4,%5,%6,%7}, {%8,%9}, {%0,%1,%2,%3};"
        : "+f"(d[0]), "+f"(d[1]), "+f"(d[2]), "+f"(d[3])
        : "r"(a[0]), "r"(a[1]), "r"(a[2]), "r"(a[3]), "r"(b[0]), "r"(b[1]));
}

__global__ void __launch_bounds__(NTHREADS, 4)
rnn_r14_kernel(const float* __restrict__ x,
               const float* __restrict__ W_ih,
               const float* __restrict__ W_hh,
               const float* __restrict__ b_ih,
               const float* __restrict__ b_hh,
               const float* __restrict__ W_out,
               const float* __restrict__ b_out,
               float* __restrict__ out)
{
    extern __shared__ float sm[];
    uint32_t* usm = (uint32_t*)sm;
    __half*   hsm = (__half*)sm;

    const int tid  = threadIdx.x;
    const int b0   = blockIdx.x * BTILE;
    const int lane = tid & 31;
    const int mg   = tid >> 5;     // warp id = m-group: W rows [mg*16, mg*16+16)
    const int gid  = lane >> 2;
    const int tig  = lane & 3;
    const int m0   = mg * 16;

    // ---- Stage combined weight Wc[64][96] fp32 at sm[0..6144) + bias ----
    for (int idx = tid; idx < HID * KCOMB; idx += NTHREADS) {
        int j = idx / KCOMB, k = idx % KCOMB;
        float v = 0.0f;
        if (k < HID)               v = W_hh[j * HID + k];
        else if (k < HID + IN_DIM) v = W_ih[j * IN_DIM + (k - HID)];
        sm[idx] = v;
    }
    if (tid < HID) sm[BIAS_OFF + tid] = b_ih[tid] + b_hh[tid];
    __syncthreads();

    // ---- W fragments (A operand, one m16k16 tile per warp), hi + scaled-lo fp16 ----
    uint32_t whi[CHUNKS][4], wlo[CHUNKS][4];
#pragma unroll
    for (int c = 0; c < CHUNKS; c++) {
#pragma unroll
        for (int r = 0; r < 4; r++) {
            int row = m0 + gid + (r & 1) * 8;
            int k0  = c * 16 + 2 * tig + (r >> 1) * 8;
            float va = sm[row * KCOMB + k0];
            float vb = sm[row * KCOMB + k0 + 1];
            __half ha = __float2half_rn(va), hb = __float2half_rn(vb);
            whi[c][r] = pack2(ha, hb);
            wlo[c][r] = pack2(
                __float2half_rn((va - __half2float(ha)) * 2048.0f),
                __float2half_rn((vb - __half2float(hb)) * 2048.0f));
        }
    }
    const float bias0 = sm[BIAS_OFF + m0 + gid];
    const float bias1 = sm[BIAS_OFF + m0 + gid + 8];
    __syncthreads();   // frag reads done; stage area reused as state

    // ---- Zero state double-buffers (h=0, pads 0) ----
    for (int idx = tid; idx < STATE_WORDS; idx += NTHREADS) sm[idx] = 0.0f;

    // ---- x loader: 56 threads, one float4 per step, 2-step-deep pipeline ----
    const bool isld = tid < 56;
    const int  xn = isld ? tid / 7 : 0;       // row 0..7
    const int  xq = isld ? tid % 7 : 0;
    const float4* xp4 = (const float4*)(x + (size_t)(b0 + xn) * TSTEPS * IN_DIM) + xq;

    float4 xr0 = make_float4(0, 0, 0, 0);     // x(t+1), stored at end of step t
    float4 xr1 = make_float4(0, 0, 0, 0);     // x(t+2), in flight

    auto store_xv = [&](int p, const float4& v) {
        int wb = p * PLANE + xn * S + 32 + 2 * xq;
        uint2 w;
        w.x = packf2(v.x, v.y);
        w.y = packf2(v.z, v.w);
        *reinterpret_cast<uint2*>(&usm[wb]) = w;
    };

    __syncthreads();                           // zero-fill visible
    if (isld) {
        float4 v0 = xp4[0];                    // x(0)
        store_xv(0, v0);
        xr0 = xp4[7];                          // x(1)
    }
    __syncthreads();

    const int n0 = 2 * tig;                    // batch rows n0, n0+1 (0..7)

    int p = 0;
    for (int t = 0; t < TSTEPS; t++) {
        // issue LDG for x(t+2): ~2-step window before consumption
        if (isld && t + 2 < TSTEPS) xr1 = xp4[(t + 2) * 7];

        // 5 independent HMMA chains: accA0/1/2 depth 2, accB1/2 depth 3
        float accA0[4], accA1[4], accA2[4], accB1[4], accB2[4];
        accA0[0] = bias0; accA0[1] = bias0; accA0[2] = bias1; accA0[3] = bias1;
#pragma unroll
        for (int r = 0; r < 4; r++) {
            accA1[r] = 0.0f; accA2[r] = 0.0f; accB1[r] = 0.0f; accB2[r] = 0.0f;
        }

        const int hbase = p * PLANE + gid * S;   // n-row = gid (0..7)
#pragma unroll
        for (int c = 0; c < CHUNKS; c++) {
            uint32_t b[2];
            b[0] = usm[hbase + c * 8 + tig];
            b[1] = usm[hbase + c * 8 + tig + 4];
            if      (c % 3 == 0) mma16(accA0, whi[c], b);
            else if (c % 3 == 1) mma16(accA1, whi[c], b);
            else                 mma16(accA2, whi[c], b);
            if (c & 1) mma16(accB1, wlo[c], b);
            else       mma16(accB2, wlo[c], b);
        }

        // v = (A0+A1) + fma(B1+B2, 2^-11, A2); tanh.approx; direct half stores
        const int q = p ^ 1;
        float v0, v1, v2, v3;
        {
            float tA0 = accA0[0] + accA1[0], tB0 = accB1[0] + accB2[0];
            float tA1 = accA0[1] + accA1[1], tB1 = accB1[1] + accB2[1];
            float tA2 = accA0[2] + accA1[2], tB2 = accB1[2] + accB2[2];
            float tA3 = accA0[3] + accA1[3], tB3 = accB1[3] + accB2[3];
            v0 = tanh_hw(tA0 + fmaf(tB0, INV2048, accA2[0]));
            v1 = tanh_hw(tA1 + fmaf(tB1, INV2048, accA2[1]));
            v2 = tanh_hw(tA2 + fmaf(tB2, INV2048, accA2[2]));
            v3 = tanh_hw(tA3 + fmaf(tB3, INV2048, accA2[3]));
        }

        {
            // halfword index = 2*(buffer word base) + j
            int hb0 = (q * PLANE + n0 * S) * 2;        // row n0
            int hb1 = hb0 + 2 * S;                     // row n0+1
            int jA = m0 + gid, jB = jA + 8;
            hsm[hb0 + jA] = __float2half_rn(v0);
            hsm[hb1 + jA] = __float2half_rn(v1);
            hsm[hb0 + jB] = __float2half_rn(v2);
            hsm[hb1 + jB] = __float2half_rn(v3);
        }

        if (isld && t + 1 < TSTEPS) store_xv(q, xr0);
        xr0 = xr1;
        __syncthreads();
        p = q;
    }

    // ---- Output projection: stage W_out past the state region ----
    for (int idx = tid; idx < OUT_DIM * HID; idx += NTHREADS) sm[WOUT_OFF + idx] = W_out[idx];
    if (tid < OUT_DIM) sm[WOUT_OFF + OUT_DIM * HID + tid] = b_out[tid];
    __syncthreads();

    const int hb = p * PLANE;
    for (int idx = tid; idx < BTILE * OUT_DIM; idx += NTHREADS) {
        int n = idx / OUT_DIM, o = idx % OUT_DIM;
        float s = sm[WOUT_OFF + OUT_DIM * HID + o];
#pragma unroll 8
        for (int jp = 0; jp < HID / 2; jp++) {
            __half2 hh = *reinterpret_cast<const __half2*>(&usm[hb + n * S + jp]);
            float2 fh = __half22float2(hh);
            s += fh.x * sm[WOUT_OFF + o * HID + 2 * jp]
               + fh.y * sm[WOUT_OFF + o * HID + 2 * jp + 1];
        }
        out[(size_t)(b0 + n) * OUT_DIM + o] = s;
    }
}

extern "C" void kernel_launch(void* const* d_in, const int* in_sizes, int n_in,
                              void* d_out, int out_size)
{
    const float* x     = (const float*)d_in[0];
    const float* W_ih  = (const float*)d_in[1];
    const float* W_hh  = (const float*)d_in[2];
    const float* b_ih  = (const float*)d_in[3];
    const float* b_hh  = (const float*)d_in[4];
    const float* W_out = (const float*)d_in[5];
    const float* b_out = (const float*)d_in[6];
    float* out = (float*)d_out;

    cudaFuncSetAttribute(rnn_r14_kernel,
                         cudaFuncAttributeMaxDynamicSharedMemorySize, SMEM_BYTES);

    dim3 grid(BATCH / BTILE);   // 512 CTAs, 8 persistent batch rows each
    dim3 block(NTHREADS);       // 4 warps, each m=16
    rnn_r14_kernel<<<grid, block, SMEM_BYTES>>>(x, W_ih, W_hh, b_ih, b_hh,
                                                W_out, b_out, out);
}